// round 3
// baseline (speedup 1.0000x reference)
#include <cuda_runtime.h>
#include <cuda_bf16.h>
#include <cstdint>

// Reference is mathematically the identity map (verified rel_err 2.9e-07):
//   [mag*cos(ph), mag*sin(ph)] == [re, im]; INV_BASIS is a scaled left
//   inverse of the full-rank forward basis; overlap-add * w^2 / ws * scale
//   reconstructs x_pad exactly; crop returns the input.
// => optimal kernel is a 20.48MB D2D copy.
//
// R1 (1 float4/thread, 5000 blocks) and R2 (cudaMemcpyAsync) both hit an
// 8.9us latency floor (L2=26%, DRAM=30%, issue=37%): MLP=1 per thread +
// ~34 block waves. This version: single resident wave (625 blocks), 8
// front-batched independent float4 loads per thread (MLP_p1=8) so L2/DRAM
// latency is covered by in-flight loads, not thread count.
// 1,280,000 float4 = 625 blocks * 256 threads * 8 exactly (no tail).

#ifndef UNROLL
#define UNROLL 8
#endif

__global__ void __launch_bounds__(256) stft_copy_mlp8(
    const float4* __restrict__ in, float4* __restrict__ out, int n4)
{
    int base = blockIdx.x * (256 * UNROLL) + threadIdx.x;

    if (base + 256 * (UNROLL - 1) < n4) {
        // fast path: all UNROLL elements valid — loads front-batched
        float4 v[UNROLL];
#pragma unroll
        for (int k = 0; k < UNROLL; k++)
            v[k] = in[base + k * 256];
#pragma unroll
        for (int k = 0; k < UNROLL; k++)
            out[base + k * 256] = v[k];
    } else {
#pragma unroll
        for (int k = 0; k < UNROLL; k++) {
            int i = base + k * 256;
            if (i < n4) out[i] = in[i];
        }
    }
}

extern "C" void kernel_launch(void* const* d_in, const int* in_sizes, int n_in,
                              void* d_out, int out_size) {
    const float* in = (const float*)d_in[0];
    float* out = (float*)d_out;

    int n = out_size;                    // 5,120,000 floats (divisible by 4)
    int n4 = n >> 2;                     // 1,280,000 float4
    int per_block = 256 * UNROLL;        // 2048
    int blocks = (n4 + per_block - 1) / per_block;  // 625 — single wave

    stft_copy_mlp8<<<blocks, 256>>>((const float4*)in, (float4*)out, n4);

    // tail floats (none for this shape: 5,120,000 % 4 == 0), handled for safety
    int done = n4 << 2;
    if (done < n) {
        // tiny remainder copy via same kernel shape is overkill; use a 1-block pass
        // (not reached for this problem's fixed shape)
        cudaMemcpyAsync(out + done, in + done, (size_t)(n - done) * sizeof(float),
                        cudaMemcpyDeviceToDevice, 0);
    }
}

// round 4
// speedup vs baseline: 1.0257x; 1.0257x over previous
#include <cuda_runtime.h>
#include <cuda_bf16.h>
#include <cstdint>

// Reference is mathematically the identity map (verified rel_err 2.9e-07):
// output (32,1,160000) == input (32,160000). Optimal kernel = 20.48MB D2D copy.
//
// R1-R3: every LDG-based copy shape (1xf4/thread, driver memcpy, MLP=8
// single-wave) hits an identical 8.9us floor with DRAM/L2/L1 all ~25-30%
// and issue 2.7-37% -- shape-invariant => bound by per-SM outstanding-miss
// capacity on the LDG path (~2.3 TB/s read cap), not by BW or issue.
//
// R4: use the TMA bulk-copy path (cp.async.bulk / UBLKCP), which has its own
// deep async queue independent of LDG MSHRs. 625 blocks x one 32KB chunk
// (exactly 20,480,000 bytes, no tail). Each block: bulk G->S load into 32KB
// static smem (mbarrier complete_tx), wait, bulk S->G store, wait_group.
// ~4.2 blocks/SM => ~135KB of reads in flight per SM vs ~8KB on LDG path.

#define CHUNK 32768

__global__ void __launch_bounds__(32) stft_tma_copy(
    const char* __restrict__ in, char* __restrict__ out, long long total)
{
    __shared__ alignas(128) char buf[CHUNK];
    __shared__ alignas(8) unsigned long long mbar;

    long long base = (long long)blockIdx.x * CHUNK;
    if (base >= total) return;
    unsigned bytes = (unsigned)((total - base) < CHUNK ? (total - base) : CHUNK);

    if (threadIdx.x != 0) return;  // single active lane; no cross-thread deps

    uint32_t s_buf = (uint32_t)__cvta_generic_to_shared(buf);
    uint32_t s_bar = (uint32_t)__cvta_generic_to_shared(&mbar);

    // init mbarrier (count=1), make it visible to the async proxy
    asm volatile("mbarrier.init.shared.b64 [%0], %1;" :: "r"(s_bar), "r"(1));
    asm volatile("fence.proxy.async.shared::cta;" ::: "memory");

    // expect the full chunk, then issue the bulk G->S copy
    asm volatile("mbarrier.arrive.expect_tx.shared.b64 _, [%0], %1;"
                 :: "r"(s_bar), "r"(bytes));
    asm volatile(
        "cp.async.bulk.shared::cluster.global.mbarrier::complete_tx::bytes "
        "[%0], [%1], %2, [%3];"
        :: "r"(s_buf), "l"(in + base), "r"(bytes), "r"(s_bar) : "memory");

    // wait for completion (phase parity 0)
    {
        uint32_t done = 0;
        while (!done) {
            asm volatile(
                "{\n\t.reg .pred p;\n\t"
                "mbarrier.try_wait.parity.acquire.cta.shared::cta.b64 p, [%1], %2, 0x989680;\n\t"
                "selp.b32 %0, 1, 0, p;\n\t}"
                : "=r"(done) : "r"(s_bar), "r"(0u) : "memory");
        }
    }
    asm volatile("fence.proxy.async.shared::cta;" ::: "memory");

    // bulk S->G store, then drain before exit
    asm volatile(
        "cp.async.bulk.global.shared::cta.bulk_group [%0], [%1], %2;"
        :: "l"(out + base), "r"(s_buf), "r"(bytes) : "memory");
    asm volatile("cp.async.bulk.commit_group;" ::: "memory");
    asm volatile("cp.async.bulk.wait_group 0;" ::: "memory");
}

extern "C" void kernel_launch(void* const* d_in, const int* in_sizes, int n_in,
                              void* d_out, int out_size) {
    const char* in = (const char*)d_in[0];
    char* out = (char*)d_out;
    long long total = (long long)out_size * sizeof(float);  // 20,480,000 bytes

    int blocks = (int)((total + CHUNK - 1) / CHUNK);        // 625
    stft_tma_copy<<<blocks, 32>>>(in, out, total);
}